// round 6
// baseline (speedup 1.0000x reference)
#include <cuda_runtime.h>
#include <cstdint>

#define THREADS 256
#define ROWS 256                    // rows per block
#define KCHUNK 32                   // floats per k-chunk
#define NCHUNK 4                    // 128 / 32
#define UNITS 8                     // 16B units per row per chunk
#define HROWS (ROWS + 1)            // incl. halo row
#define STAGE_ROWS (2 * HROWS)      // X rows [0,257) then theta rows [257,514)
#define STAGE_UNITS (STAGE_ROWS * UNITS)   // 4112 float4 units
#define STAGE_BYTES (STAGE_UNITS * 16)     // 65792 B

// smem map (bytes):
//   [0, 2*STAGE_BYTES)                  : double-buffered tile stages
//   [2*STAGE_BYTES, +1024)              : xi (2 x 128 floats = 64 float4)
//   [.. , +257*8)                       : V exchange (float2 x 257)
#define SMEM_XI_OFF   (2 * STAGE_BYTES)
#define SMEM_V_OFF    (2 * STAGE_BYTES + 1024)
#define SMEM_TOTAL    (SMEM_V_OFF + HROWS * 8)

__device__ __forceinline__ void cp_async16(uint32_t dst_smem, const void* src) {
    asm volatile("cp.async.cg.shared.global [%0], [%1], 16;\n"
                 :: "r"(dst_smem), "l"(src));
}
__device__ __forceinline__ void cp_commit() {
    asm volatile("cp.async.commit_group;\n");
}
template <int NN>
__device__ __forceinline__ void cp_wait() {
    asm volatile("cp.async.wait_group %0;\n" :: "n"(NN));
}

__device__ __forceinline__ void acc4(float& a, float4 x, float4 y) {
    a = fmaf(x.x, y.x, a);
    a = fmaf(x.y, y.y, a);
    a = fmaf(x.z, y.z, a);
    a = fmaf(x.w, y.w, a);
}

__global__ __launch_bounds__(THREADS, 1)
void smf_kernel(const float* __restrict__ X,
                const float* __restrict__ theta,
                const float* __restrict__ f_bias,
                const float* __restrict__ xi,
                const float* __restrict__ g_bias,
                float* __restrict__ out,
                int N)
{
    extern __shared__ char smem[];
    float4* __restrict__ buf = reinterpret_cast<float4*>(smem);
    float4* __restrict__ xis = reinterpret_cast<float4*>(smem + SMEM_XI_OFF);
    float2* __restrict__ vsh = reinterpret_cast<float2*>(smem + SMEM_V_OFF);

    const int tid  = threadIdx.x;
    const int base = blockIdx.x * ROWS;

    const float4* __restrict__ X4  = reinterpret_cast<const float4*>(X);
    const float4* __restrict__ T4  = reinterpret_cast<const float4*>(theta);
    const float4* __restrict__ XI4 = reinterpret_cast<const float4*>(xi);

    const uint32_t smem_u32 = (uint32_t)__cvta_generic_to_shared(smem);

    // Load xi (1KB) into smem once; visible after first __syncthreads below.
    if (tid < 64)
        xis[tid] = XI4[tid];

    // ---- cp.async producer for one k-chunk into stage s ----
    auto issue_chunk = [&](int c, int s) {
        const int colbase = c * UNITS;             // float4 column offset in row
        #pragma unroll
        for (int it = 0; it < 17; it++) {
            int idx = tid + it * THREADS;
            if (idx < STAGE_UNITS) {
                int row = idx >> 3;                // buffer row 0..513
                int u   = idx & 7;
                int r   = row;
                const float4* srcmat = X4;
                if (row >= HROWS) { r = row - HROWS; srcmat = T4; }
                int grow = base + r;
                if (grow >= N) grow -= N;          // only last block's halo wraps
                const float4* src = srcmat + (size_t)grow * 32 + colbase + u;
                int su = u ^ (row & 7);            // swizzle
                uint32_t dst = smem_u32 +
                    (uint32_t)((s * STAGE_UNITS + (row << 3) + su) * 16);
                cp_async16(dst, src);
            }
        }
        cp_commit();
    };

    float pd = 0.0f, ps = 0.0f, q0 = 0.0f, q1 = 0.0f;
    float qh0 = 0.0f, qh1 = 0.0f;                  // halo row (thread 0 only)

    // Precomputed buffer row indices for this thread
    const int rx = tid;                 // X row
    const int rd = HROWS + tid;         // theta diag row
    const int rs = HROWS + tid + 1;     // theta sup row
    const int rh = ROWS;                // X halo row (row 256)

    issue_chunk(0, 0);

    #pragma unroll
    for (int c = 0; c < NCHUNK; c++) {
        const int s = c & 1;
        if (c + 1 < NCHUNK) {
            issue_chunk(c + 1, (c + 1) & 1);
            cp_wait<1>();
        } else {
            cp_wait<0>();
        }
        __syncthreads();

        const float4* __restrict__ st = buf + s * STAGE_UNITS;
        #pragma unroll
        for (int u = 0; u < UNITS; u++) {
            float4 xv = st[(rx << 3) + (u ^ (rx & 7))];
            float4 td = st[(rd << 3) + (u ^ (rd & 7))];
            float4 ts = st[(rs << 3) + (u ^ (rs & 7))];
            float4 w0 = xis[c * UNITS + u];          // uniform (broadcast)
            float4 w1 = xis[32 + c * UNITS + u];
            acc4(pd, xv, td);
            acc4(ps, xv, ts);
            acc4(q0, xv, w0);
            acc4(q1, xv, w1);
        }
        if (tid == 0) {
            #pragma unroll
            for (int u = 0; u < UNITS; u++) {
                float4 xh = st[(rh << 3) + (u ^ (rh & 7))];
                float4 w0 = xis[c * UNITS + u];
                float4 w1 = xis[32 + c * UNITS + u];
                acc4(qh0, xh, w0);
                acc4(qh1, xh, w1);
            }
        }
        __syncthreads();   // stage s is free for chunk c+2
    }

    // ---- Epilogue ----
    const float gb0 = g_bias[0];
    const float gb1 = g_bias[1];

    const int i  = base + tid;
    int in = i + 1;
    if (in >= N) in -= N;

    const float wd = fmaxf(pd + f_bias[i],  0.0f);
    const float ws = fmaxf(ps + f_bias[in], 0.0f);
    const float v0 = fmaxf(q0 + gb0, 0.0f);
    const float v1 = fmaxf(q1 + gb1, 0.0f);

    vsh[tid] = make_float2(v0, v1);
    if (tid == 0)
        vsh[ROWS] = make_float2(fmaxf(qh0 + gb0, 0.0f), fmaxf(qh1 + gb1, 0.0f));
    __syncthreads();

    const float2 vn = vsh[tid + 1];
    float2 o;
    o.x = wd * v0 + ws * vn.x;
    o.y = wd * v1 + ws * vn.y;
    reinterpret_cast<float2*>(out)[i] = o;
}

extern "C" void kernel_launch(void* const* d_in, const int* in_sizes, int n_in,
                              void* d_out, int out_size)
{
    const float* X      = (const float*)d_in[0];
    const float* theta  = (const float*)d_in[1];
    const float* f_bias = (const float*)d_in[2];
    const float* xi     = (const float*)d_in[3];
    const float* g_bias = (const float*)d_in[4];
    float* out = (float*)d_out;

    const int N = in_sizes[2];            // f_bias has N elements
    const int blocks = N / ROWS;          // 524288 / 256 = 2048

    cudaFuncSetAttribute(smf_kernel,
                         cudaFuncAttributeMaxDynamicSharedMemorySize,
                         SMEM_TOTAL);

    smf_kernel<<<blocks, THREADS, SMEM_TOTAL>>>(X, theta, f_bias, xi, g_bias, out, N);
}

// round 7
// speedup vs baseline: 1.0233x; 1.0233x over previous
#include <cuda_runtime.h>
#include <cstdint>

#define WARPS_PER_BLOCK 8
#define ROWS_PER_WARP 16
#define ROWS_PER_BLOCK (WARPS_PER_BLOCK * ROWS_PER_WARP)   // 128

__device__ __forceinline__ float dot4(float4 a, float4 b) {
    return a.x*b.x + a.y*b.y + a.z*b.z + a.w*b.w;
}

// Packed reduction of 4 per-lane values across the warp. 9 SHFL total.
// PD returned valid on lane 0 only; PS/Q0/Q1 broadcast to all lanes.
__device__ __forceinline__ void quad_reduce(float pd, float ps, float q0, float q1,
                                            int lane,
                                            float& PD, float& PS, float& Q0, float& Q1)
{
    const unsigned FULL = 0xFFFFFFFFu;
    const bool lo16 = (lane & 16) == 0;

    float a  = lo16 ? q0 : pd;
    float b  = lo16 ? q1 : ps;
    float ra = __shfl_xor_sync(FULL, a, 16);
    float rb = __shfl_xor_sync(FULL, b, 16);
    float u  = (lo16 ? pd : q0) + ra;
    float v  = (lo16 ? ps : q1) + rb;

    const bool lo8 = (lane & 8) == 0;
    float c  = lo8 ? v : u;
    float rc = __shfl_xor_sync(FULL, c, 8);
    float s  = (lo8 ? u : v) + rc;

    s += __shfl_xor_sync(FULL, s, 4);
    s += __shfl_xor_sync(FULL, s, 2);
    s += __shfl_xor_sync(FULL, s, 1);

    PD = s;                           // valid on lane 0
    PS = __shfl_sync(FULL, s, 8);
    Q0 = __shfl_sync(FULL, s, 16);
    Q1 = __shfl_sync(FULL, s, 24);
}

__global__ __launch_bounds__(WARPS_PER_BLOCK * 32, 6)
void smf_kernel(const float* __restrict__ X,
                const float* __restrict__ theta,
                const float* __restrict__ f_bias,
                const float* __restrict__ xi,
                const float* __restrict__ g_bias,
                float* __restrict__ out,
                int N)
{
    __shared__ float4 xis[64];                          // xi: 2 x 128 floats
    __shared__ float2 Vfirst[WARPS_PER_BLOCK];          // V of each warp's first row
    __shared__ float2 obuf[WARPS_PER_BLOCK][ROWS_PER_WARP];

    const int warp = threadIdx.x >> 5;
    const int lane = threadIdx.x & 31;
    const int base = (blockIdx.x * WARPS_PER_BLOCK + warp) * ROWS_PER_WARP;

    const float4* __restrict__ X4  = reinterpret_cast<const float4*>(X);
    const float4* __restrict__ T4  = reinterpret_cast<const float4*>(theta);
    const float4* __restrict__ XI4 = reinterpret_cast<const float4*>(xi);

    if (threadIdx.x < 64)
        xis[threadIdx.x] = XI4[threadIdx.x];

    const float gb0 = g_bias[0];
    const float gb1 = g_bias[1];

    // Pipeline state (depth 1): current X row, diag theta, sup theta
    float4 x_cur = __ldcs(X4 + (size_t)base * 32 + lane);
    float4 t_cur = __ldcs(T4 + (size_t)base * 32 + lane);
    float4 t_nxt = __ldcs(T4 + (size_t)(base + 1) * 32 + lane);
    float  fb_cur = __ldg(f_bias + base);

    __syncthreads();   // xis visible

    float wd_p = 0.0f, ws_p = 0.0f, v0_p = 0.0f, v1_p = 0.0f;

    #pragma unroll
    for (int r = 0; r < ROWS_PER_WARP; r++) {
        const int row = base + r;
        int rn = row + 1;
        if (rn >= N) rn -= N;

        // Prefetch next iteration (distance 1)
        float4 x_nx, t_nx2;
        if (r < ROWS_PER_WARP - 1) {
            x_nx = __ldcs(X4 + (size_t)(row + 1) * 32 + lane);
            int i2 = row + 2;
            if (i2 >= N) i2 -= N;
            t_nx2 = __ldcs(T4 + (size_t)i2 * 32 + lane);
        }
        const float fb_nxt = __ldg(f_bias + rn);

        const float4 w0 = xis[lane];
        const float4 w1 = xis[32 + lane];

        float pd = dot4(x_cur, t_cur);
        float ps = dot4(x_cur, t_nxt);
        float q0 = dot4(x_cur, w0);
        float q1 = dot4(x_cur, w1);

        float PD, PS, Q0, Q1;
        quad_reduce(pd, ps, q0, q1, lane, PD, PS, Q0, Q1);

        const float wd = fmaxf(PD + fb_cur, 0.0f);   // lane 0 valid
        const float ws = fmaxf(PS + fb_nxt, 0.0f);
        const float v0 = fmaxf(Q0 + gb0, 0.0f);
        const float v1 = fmaxf(Q1 + gb1, 0.0f);

        if (r == 0) {
            if (lane == 0)
                Vfirst[warp] = make_float2(v0, v1);
        } else if (lane == 0) {
            obuf[warp][r - 1] = make_float2(wd_p * v0_p + ws_p * v0,
                                            wd_p * v1_p + ws_p * v1);
        }

        wd_p = wd; ws_p = ws; v0_p = v0; v1_p = v1;
        fb_cur = fb_nxt;
        if (r < ROWS_PER_WARP - 1) {
            x_cur = x_nx;
            t_cur = t_nxt;
            t_nxt = t_nx2;
        }
    }

    // Final row of this warp needs V[base + ROWS_PER_WARP]
    float2 vnext = make_float2(0.0f, 0.0f);
    if (warp == WARPS_PER_BLOCK - 1) {
        int h = base + ROWS_PER_WARP;
        if (h >= N) h -= N;
        const float4 xh = __ldcs(X4 + (size_t)h * 32 + lane);
        const float4 w0 = xis[lane];
        const float4 w1 = xis[32 + lane];
        float h0 = dot4(xh, w0);
        float h1 = dot4(xh, w1);
        float H0, H1, D0, D1;
        quad_reduce(h0, h1, 0.0f, 0.0f, lane, H0, H1, D0, D1);
        if (lane == 0)
            vnext = make_float2(fmaxf(H0 + gb0, 0.0f), fmaxf(H1 + gb1, 0.0f));
    }
    __syncthreads();

    if (lane == 0) {
        if (warp < WARPS_PER_BLOCK - 1)
            vnext = Vfirst[warp + 1];
        obuf[warp][ROWS_PER_WARP - 1] = make_float2(wd_p * v0_p + ws_p * vnext.x,
                                                    wd_p * v1_p + ws_p * vnext.y);
    }
    __syncwarp();

    // Coalesced store: 16 lanes write the warp's 16 float2 results (128B)
    if (lane < ROWS_PER_WARP)
        reinterpret_cast<float2*>(out)[base + lane] = obuf[warp][lane];
}

extern "C" void kernel_launch(void* const* d_in, const int* in_sizes, int n_in,
                              void* d_out, int out_size)
{
    const float* X      = (const float*)d_in[0];
    const float* theta  = (const float*)d_in[1];
    const float* f_bias = (const float*)d_in[2];
    const float* xi     = (const float*)d_in[3];
    const float* g_bias = (const float*)d_in[4];
    float* out = (float*)d_out;

    const int N = in_sizes[2];                   // f_bias has N elements
    const int blocks = N / ROWS_PER_BLOCK;       // 524288 / 128 = 4096

    smf_kernel<<<blocks, WARPS_PER_BLOCK * 32>>>(X, theta, f_bias, xi, g_bias, out, N);
}